// round 8
// baseline (speedup 1.0000x reference)
#include <cuda_runtime.h>
#include <math.h>
#include <stdint.h>

#define NTOK   2048
#define DMODEL 2048
#define KVD    512
#define NHEADS 16
#define HDIM   128

static __device__ float g_Q[NTOK * DMODEL];
static __device__ float g_K[NTOK * KVD];
static __device__ float g_V[NTOK * KVD];
static __device__ float g_S[(size_t)NHEADS * NTOK * NTOK];
static __device__ float g_C[NTOK * DMODEL];
static __device__ float g_partial[(size_t)NHEADS * 16 * NTOK];  // (head, coltile, row)
static __device__ float g_inv[NHEADS * NTOK];                   // 1/rowsum

#define PSTR 40   // paired-k row stride (words); 40 % 32 == 8 -> conflict-free LDS.64
#define BSN  136  // NN B-tile row stride (words); conflict-free scalar frags

__device__ __forceinline__ uint32_t f2tf32(float x) {
    uint32_t r;
    asm("cvt.rna.tf32.f32 %0, %1;" : "=r"(r) : "f"(x));
    return r;
}

__device__ __forceinline__ void mma_tf32(float c[4], const uint32_t a[4],
                                         uint32_t b0, uint32_t b1) {
    asm volatile(
        "mma.sync.aligned.m16n8k8.row.col.f32.tf32.tf32.f32 "
        "{%0,%1,%2,%3}, {%4,%5,%6,%7}, {%8,%9}, {%0,%1,%2,%3};"
        : "+f"(c[0]), "+f"(c[1]), "+f"(c[2]), "+f"(c[3])
        : "r"(a[0]), "r"(a[1]), "r"(a[2]), "r"(a[3]), "r"(b0), "r"(b1));
}

// ---------------------------------------------------------------------------
// TF32 tensor-core GEMM. 128x128 block tile, 256 threads (8 warps, 4m x 2n),
// warp tile 32x64, K chunk 32, register-staged prefetch, static smem.
// A (and B when BT) stored in paired-k layout: word(k) = (k>>3)*8 + 2(k&3) +
// ((k>>2)&1), so fragment k-pairs (t, t+4) are one LDS.64.
// MODE 0: plain store. MODE 1 (qk): exp(scale*acc) + causal mask + row
// partial sums. MODE 2 (pv): acc *= invsum[localrow].
// ---------------------------------------------------------------------------
template <bool BT, int MODE>
__device__ __forceinline__ void tf32gemm(const float* __restrict__ A,
                                         const float* __restrict__ B,
                                         float* __restrict__ C,
                                         int Kdim, int lda, int ldb, int ldc,
                                         float* __restrict__ partialOut,
                                         const float* __restrict__ invsum,
                                         int rowg0, int colg0)
{
    __shared__ uint32_t As[128 * PSTR];
    __shared__ uint32_t Bs[BT ? (128 * PSTR) : (32 * BSN)];
    __shared__ float part[256];                      // MODE 1 only
    const int tid  = threadIdx.x;
    const int lane = tid & 31, wid = tid >> 5;
    const int wm = wid & 3, wn = wid >> 2;
    const int g = lane >> 2, t = lane & 3;

    float acc[2][8][4];
#pragma unroll
    for (int mt = 0; mt < 2; ++mt)
#pragma unroll
        for (int nt = 0; nt < 8; ++nt)
#pragma unroll
            for (int j = 0; j < 4; ++j) acc[mt][nt][j] = 0.f;

    float4 areg[4], breg[4];

    // prologue: stage chunk 0
#pragma unroll
    for (int i = 0; i < 4; ++i) {
        int idx = tid + (i << 8);
        int r = idx >> 3, kk = (idx & 7) << 2;
        areg[i] = *reinterpret_cast<const float4*>(A + (size_t)r * lda + kk);
        if (BT) {
            breg[i] = *reinterpret_cast<const float4*>(B + (size_t)r * ldb + kk);
        } else {
            int rb = idx >> 5, n = (idx & 31) << 2;
            breg[i] = *reinterpret_cast<const float4*>(B + (size_t)rb * ldb + n);
        }
    }

    for (int k0 = 0; k0 < Kdim; k0 += 32) {
        // commit staged chunk to smem (tf32-converted, paired-k layout)
#pragma unroll
        for (int i = 0; i < 4; ++i) {
            int idx = tid + (i << 8);
            int r = idx >> 3, c = idx & 7;
            int base = r * PSTR + ((c >> 1) << 3) + (c & 1);  // w(4c) = 8(c>>1)+(c&1)
            As[base + 0] = f2tf32(areg[i].x);
            As[base + 2] = f2tf32(areg[i].y);
            As[base + 4] = f2tf32(areg[i].z);
            As[base + 6] = f2tf32(areg[i].w);
            if (BT) {
                Bs[base + 0] = f2tf32(breg[i].x);
                Bs[base + 2] = f2tf32(breg[i].y);
                Bs[base + 4] = f2tf32(breg[i].z);
                Bs[base + 6] = f2tf32(breg[i].w);
            } else {
                int rb = idx >> 5, n = (idx & 31) << 2;
                Bs[rb * BSN + n + 0] = f2tf32(breg[i].x);
                Bs[rb * BSN + n + 1] = f2tf32(breg[i].y);
                Bs[rb * BSN + n + 2] = f2tf32(breg[i].z);
                Bs[rb * BSN + n + 3] = f2tf32(breg[i].w);
            }
        }
        __syncthreads();

        // prefetch next chunk while computing this one
        if (k0 + 32 < Kdim) {
            const float* An = A + k0 + 32;
            const float* Bn = BT ? (B + k0 + 32) : (B + (size_t)(k0 + 32) * ldb);
#pragma unroll
            for (int i = 0; i < 4; ++i) {
                int idx = tid + (i << 8);
                int r = idx >> 3, kk = (idx & 7) << 2;
                areg[i] = *reinterpret_cast<const float4*>(An + (size_t)r * lda + kk);
                if (BT) {
                    breg[i] = *reinterpret_cast<const float4*>(Bn + (size_t)r * ldb + kk);
                } else {
                    int rb = idx >> 5, n = (idx & 31) << 2;
                    breg[i] = *reinterpret_cast<const float4*>(Bn + (size_t)rb * ldb + n);
                }
            }
        }

        // compute: 4 k-steps of 8
#pragma unroll
        for (int ks = 0; ks < 4; ++ks) {
            const int kb = ks << 3;
            uint32_t af[2][4];
#pragma unroll
            for (int mt = 0; mt < 2; ++mt) {
                int m = wm * 32 + mt * 16;
                uint2 p0 = *reinterpret_cast<const uint2*>(&As[(m + g) * PSTR + kb + 2 * t]);
                uint2 p1 = *reinterpret_cast<const uint2*>(&As[(m + g + 8) * PSTR + kb + 2 * t]);
                af[mt][0] = p0.x; af[mt][1] = p1.x;
                af[mt][2] = p0.y; af[mt][3] = p1.y;
            }
#pragma unroll
            for (int nt = 0; nt < 8; ++nt) {
                int n = wn * 64 + nt * 8;
                uint32_t b0, b1;
                if (BT) {
                    uint2 pb = *reinterpret_cast<const uint2*>(&Bs[(n + g) * PSTR + kb + 2 * t]);
                    b0 = pb.x; b1 = pb.y;
                } else {
                    b0 = Bs[(kb + t) * BSN + n + g];
                    b1 = Bs[(kb + t + 4) * BSN + n + g];
                }
                mma_tf32(acc[0][nt], af[0], b0, b1);
                mma_tf32(acc[1][nt], af[1], b0, b1);
            }
        }
        __syncthreads();
    }

    if (MODE == 1) {
        const float scale = 0.08838834764831845f;   // 1/sqrt(128)
        float rp[4] = {0.f, 0.f, 0.f, 0.f};         // [mt*2 + half]
#pragma unroll
        for (int mt = 0; mt < 2; ++mt)
#pragma unroll
            for (int nt = 0; nt < 8; ++nt)
#pragma unroll
                for (int j = 0; j < 4; ++j) {
                    int lr = wm * 32 + mt * 16 + g + ((j >> 1) << 3);
                    int cg = colg0 + wn * 64 + nt * 8 + (t << 1) + (j & 1);
                    int rg = rowg0 + lr;
                    float e = (cg <= rg) ? __expf(acc[mt][nt][j] * scale) : 0.f;
                    acc[mt][nt][j] = e;
                    rp[mt * 2 + (j >> 1)] += e;
                }
#pragma unroll
        for (int i = 0; i < 4; ++i) {
            rp[i] += __shfl_xor_sync(0xffffffffu, rp[i], 1);
            rp[i] += __shfl_xor_sync(0xffffffffu, rp[i], 2);
        }
        if (t == 0) {
#pragma unroll
            for (int mt = 0; mt < 2; ++mt)
#pragma unroll
                for (int h2 = 0; h2 < 2; ++h2)
                    part[wn * 128 + wm * 32 + mt * 16 + g + (h2 << 3)] = rp[mt * 2 + h2];
        }
        __syncthreads();
        if (tid < 128) partialOut[tid] = part[tid] + part[128 + tid];
    }
    if (MODE == 2) {
#pragma unroll
        for (int mt = 0; mt < 2; ++mt) {
            float i0 = invsum[wm * 32 + mt * 16 + g];
            float i1 = invsum[wm * 32 + mt * 16 + g + 8];
#pragma unroll
            for (int nt = 0; nt < 8; ++nt) {
                acc[mt][nt][0] *= i0; acc[mt][nt][1] *= i0;
                acc[mt][nt][2] *= i1; acc[mt][nt][3] *= i1;
            }
        }
    }

    // epilogue store
#pragma unroll
    for (int mt = 0; mt < 2; ++mt)
#pragma unroll
        for (int nt = 0; nt < 8; ++nt) {
            int row = wm * 32 + mt * 16 + g;
            int col = wn * 64 + nt * 8 + (t << 1);
            *reinterpret_cast<float2*>(C + (size_t)row * ldc + col) =
                make_float2(acc[mt][nt][0], acc[mt][nt][1]);
            *reinterpret_cast<float2*>(C + (size_t)(row + 8) * ldc + col) =
                make_float2(acc[mt][nt][2], acc[mt][nt][3]);
        }
}

// ---- Q projection ----------------------------------------------------------
__global__ void __launch_bounds__(256, 2)
proj_q_kernel(const float* __restrict__ X, const float* __restrict__ Wq)
{
    const int brow = blockIdx.y << 7, bcol = blockIdx.x << 7;
    tf32gemm<false, 0>(X + (size_t)brow * DMODEL, Wq + bcol,
                       g_Q + (size_t)brow * DMODEL + bcol,
                       DMODEL, DMODEL, DMODEL, DMODEL, nullptr, nullptr, 0, 0);
}

// ---- K / V projections -----------------------------------------------------
__global__ void __launch_bounds__(256, 2)
proj_kv_kernel(const float* __restrict__ X,
               const float* __restrict__ Wk,
               const float* __restrict__ Wv)
{
    const int brow = blockIdx.y << 7, bcol = blockIdx.x << 7;
    const float* W = (blockIdx.z == 0) ? Wk : Wv;
    float* O       = (blockIdx.z == 0) ? g_K : g_V;
    tf32gemm<false, 0>(X + (size_t)brow * DMODEL, W + bcol,
                       O + (size_t)brow * KVD + bcol,
                       DMODEL, DMODEL, KVD, KVD, nullptr, nullptr, 0, 0);
}

// ---- RoPE (interleaved), in place on g_Q and g_K ---------------------------
__global__ void rope_kernel()
{
    int idx = blockIdx.x * blockDim.x + threadIdx.x;
    const int qpairs = NTOK * (DMODEL / 2);
    float* ptr;
    int t, p;
    if (idx < qpairs) {
        t = idx >> 10; int c = idx & 1023; p = c & 63;
        ptr = g_Q + (size_t)t * DMODEL + (c << 1);
    } else {
        idx -= qpairs;
        if (idx >= NTOK * (KVD / 2)) return;
        t = idx >> 8; int c = idx & 255; p = c & 63;
        ptr = g_K + (size_t)t * KVD + (c << 1);
    }
    double inv = exp(-(double)p * (9.210340371976184 / 64.0));
    float ang = (float)((double)t * inv);
    float cs = cosf(ang), sn = sinf(ang);
    float xe = ptr[0], xo = ptr[1];
    ptr[0] = xe * cs - xo * sn;
    ptr[1] = xe * sn + xo * cs;
}

// ---- scores + exp + row partials -------------------------------------------
__global__ void __launch_bounds__(256, 2)
qk_kernel()
{
    if (blockIdx.x > blockIdx.y) return;
    const int h = blockIdx.z, brow = blockIdx.y << 7, bcol = blockIdx.x << 7;
    const int kvh = h >> 2, gs = h & 3;
    tf32gemm<true, 1>(g_Q + (size_t)brow * DMODEL + gs * 512 + kvh * 128,
                      g_K + (size_t)bcol * KVD + kvh * 128,
                      g_S + (size_t)h * NTOK * NTOK + (size_t)brow * NTOK + bcol,
                      HDIM, DMODEL, KVD, NTOK,
                      g_partial + ((size_t)h * 16 + blockIdx.x) * NTOK + brow,
                      nullptr, brow, bcol);
}

// ---- reduce per-tile partials to 1/rowsum ----------------------------------
__global__ void __launch_bounds__(256)
rowsum_kernel()
{
    const int idx = blockIdx.x * 256 + threadIdx.x;   // 0..32767
    const int h = idx >> 11, row = idx & 2047;
    const int ntile = (row >> 7) + 1;
    float s = 0.f;
    for (int tt = 0; tt < ntile; ++tt)
        s += g_partial[((size_t)h * 16 + tt) * NTOK + row];
    g_inv[idx] = 1.f / s;
}

// ---- context: C_h = (P_h @ V_h) * inv[row] ---------------------------------
__global__ void __launch_bounds__(256, 2)
pv_kernel()
{
    const int h = blockIdx.z, brow = blockIdx.y << 7;
    const int kvh = h >> 2;
    tf32gemm<false, 2>(g_S + (size_t)h * NTOK * NTOK + (size_t)brow * NTOK,
                       g_V + kvh * 128,
                       g_C + (size_t)brow * DMODEL + h * 128,
                       brow + 128, NTOK, KVD, DMODEL,
                       nullptr, g_inv + h * NTOK + brow, 0, 0);
}

// ---- output projection -----------------------------------------------------
__global__ void __launch_bounds__(256, 2)
out_kernel(const float* __restrict__ Wo, float* __restrict__ out)
{
    const int brow = blockIdx.y << 7, bcol = blockIdx.x << 7;
    tf32gemm<false, 0>(g_C + (size_t)brow * DMODEL, Wo + bcol,
                       out + (size_t)brow * DMODEL + bcol,
                       DMODEL, DMODEL, DMODEL, DMODEL, nullptr, nullptr, 0, 0);
}

extern "C" void kernel_launch(void* const* d_in, const int* in_sizes, int n_in,
                              void* d_out, int out_size)
{
    (void)in_sizes; (void)n_in; (void)out_size;
    const float* x  = (const float*)d_in[0];
    const float* Wq = (const float*)d_in[1];
    const float* Wk = (const float*)d_in[2];
    const float* Wv = (const float*)d_in[3];
    const float* Wo = (const float*)d_in[4];
    float* out = (float*)d_out;

    proj_q_kernel<<<dim3(DMODEL / 128, NTOK / 128), 256>>>(x, Wq);
    proj_kv_kernel<<<dim3(KVD / 128, NTOK / 128, 2), 256>>>(x, Wk, Wv);

    const int total_pairs = NTOK * (DMODEL / 2) + NTOK * (KVD / 2);
    rope_kernel<<<(total_pairs + 255) / 256, 256>>>();

    qk_kernel<<<dim3(NTOK / 128, NTOK / 128, NHEADS), 256>>>();
    rowsum_kernel<<<NHEADS * NTOK / 256, 256>>>();
    pv_kernel<<<dim3(1, NTOK / 128, NHEADS), 256>>>();
    out_kernel<<<dim3(DMODEL / 128, NTOK / 128), 256>>>(Wo, out);
}

// round 11
// speedup vs baseline: 1.3480x; 1.3480x over previous
#include <cuda_runtime.h>
#include <math.h>
#include <stdint.h>

#define NTOK   2048
#define DMODEL 2048
#define KVD    512
#define NHEADS 16
#define HDIM   128

static __device__ float g_Q[NTOK * DMODEL];
static __device__ float g_K[NTOK * KVD];
static __device__ float g_V[NTOK * KVD];
static __device__ float g_S[(size_t)NHEADS * NTOK * NTOK];
static __device__ float g_C[NTOK * DMODEL];
static __device__ float g_partial[(size_t)NHEADS * 16 * NTOK];  // (head, coltile, row)
static __device__ float g_inv[NHEADS * NTOK];                   // 1/rowsum

#define BSN   136                 // NN B-tile row stride (words); conflict-free frags
#define ASZ   (128 * 36)          // one A buffer (words)
#define BSZ_T (128 * 36)          // one B buffer, BT path
#define BSZ_N (32 * BSN)          // one B buffer, NN path
// dynamic smem: As0, As1, Bs0, Bs1
#define SMEM_BYTES ((2 * ASZ + 2 * BSZ_T) * 4)   // 73728 (BT is the max)

__device__ __forceinline__ uint32_t f2tf32(float x) {
    uint32_t r;
    asm("cvt.rna.tf32.f32 %0, %1;" : "=r"(r) : "f"(x));
    return r;
}

__device__ __forceinline__ void mma_tf32(float c[4], const uint32_t a[4],
                                         uint32_t b0, uint32_t b1) {
    asm volatile(
        "mma.sync.aligned.m16n8k8.row.col.f32.tf32.tf32.f32 "
        "{%0,%1,%2,%3}, {%4,%5,%6,%7}, {%8,%9}, {%0,%1,%2,%3};"
        : "+f"(c[0]), "+f"(c[1]), "+f"(c[2]), "+f"(c[3])
        : "r"(a[0]), "r"(a[1]), "r"(a[2]), "r"(a[3]), "r"(b0), "r"(b1));
}

// ---------------------------------------------------------------------------
// TF32 tensor-core GEMM. 128x128 block tile, 256 threads (8 warps, 4m x 2n),
// warp tile 32x64, K chunk 32. Double-buffered smem (compile-time offsets),
// ONE __syncthreads per chunk: STS of chunk c+1 overlaps MMAs of chunk c.
// Fragment/staging layouts identical to the proven 709us kernel.
// MODE 0: plain store. MODE 1 (qk): exp+mask+row partials. MODE 2 (pv): *inv.
// Requires nChunks even (all call sites satisfy this).
// ---------------------------------------------------------------------------
template <bool BT, int MODE>
__device__ __forceinline__ void tf32gemm(const float* __restrict__ A,
                                         const float* __restrict__ B,
                                         float* __restrict__ C,
                                         int Kdim, int lda, int ldb, int ldc,
                                         float* __restrict__ partialOut,
                                         const float* __restrict__ invsum,
                                         int rowg0, int colg0)
{
    extern __shared__ uint32_t dsm[];
    uint32_t* const AsA[2] = { dsm, dsm + ASZ };
    uint32_t* const BsA[2] = { dsm + 2 * ASZ,
                               dsm + 2 * ASZ + (BT ? BSZ_T : BSZ_N) };
    __shared__ float part[256];                      // MODE 1 only
    const int tid  = threadIdx.x;
    const int lane = tid & 31, wid = tid >> 5;
    const int wm = wid & 3, wn = wid >> 2;
    const int g = lane >> 2, t = lane & 3;
    const int nChunks = Kdim >> 5;

    float acc[2][8][4];
#pragma unroll
    for (int mt = 0; mt < 2; ++mt)
#pragma unroll
        for (int nt = 0; nt < 8; ++nt)
#pragma unroll
            for (int j = 0; j < 4; ++j) acc[mt][nt][j] = 0.f;

    // per-thread staging coordinates (fixed)
    const int r8  = tid >> 3, k8 = (tid & 7) << 2;       // A / BT-B staging
    const int rb5 = tid >> 5, n5 = (tid & 31) << 2;      // NN-B staging

    float4 areg[4], breg[4];

    // ---- helpers as macros so buf is compile-time ---------------------------
#define LDG_CHUNK(cc)                                                          \
    do {                                                                       \
        const float* An = A + (cc) * 32;                                       \
        const float* Bn = BT ? (B + (cc) * 32) : (B + (size_t)((cc) * 32) * ldb); \
        _Pragma("unroll")                                                      \
        for (int i = 0; i < 4; ++i) {                                          \
            int rr = r8 + (i << 5);                                            \
            areg[i] = *reinterpret_cast<const float4*>(An + (size_t)rr * lda + k8); \
            if (BT) {                                                          \
                breg[i] = *reinterpret_cast<const float4*>(Bn + (size_t)rr * ldb + k8); \
            } else {                                                           \
                int rbb = rb5 + (i << 3);                                      \
                breg[i] = *reinterpret_cast<const float4*>(Bn + (size_t)rbb * ldb + n5); \
            }                                                                  \
        }                                                                      \
    } while (0)

#define STS_CHUNK(BUF)                                                         \
    do {                                                                       \
        uint32_t* As = AsA[BUF];                                               \
        uint32_t* Bs = BsA[BUF];                                               \
        _Pragma("unroll")                                                      \
        for (int i = 0; i < 4; ++i) {                                          \
            int rr = r8 + (i << 5);                                            \
            As[rr * 36 + k8 + 0] = f2tf32(areg[i].x);                          \
            As[rr * 36 + k8 + 1] = f2tf32(areg[i].y);                          \
            As[rr * 36 + k8 + 2] = f2tf32(areg[i].z);                          \
            As[rr * 36 + k8 + 3] = f2tf32(areg[i].w);                          \
            if (BT) {                                                          \
                Bs[rr * 36 + k8 + 0] = f2tf32(breg[i].x);                      \
                Bs[rr * 36 + k8 + 1] = f2tf32(breg[i].y);                      \
                Bs[rr * 36 + k8 + 2] = f2tf32(breg[i].z);                      \
                Bs[rr * 36 + k8 + 3] = f2tf32(breg[i].w);                      \
            } else {                                                           \
                int rbb = rb5 + (i << 3);                                      \
                Bs[rbb * BSN + n5 + 0] = f2tf32(breg[i].x);                    \
                Bs[rbb * BSN + n5 + 1] = f2tf32(breg[i].y);                    \
                Bs[rbb * BSN + n5 + 2] = f2tf32(breg[i].z);                    \
                Bs[rbb * BSN + n5 + 3] = f2tf32(breg[i].w);                    \
            }                                                                  \
        }                                                                      \
    } while (0)

#define COMPUTE_CHUNK(BUF)                                                     \
    do {                                                                       \
        uint32_t* As = AsA[BUF];                                               \
        uint32_t* Bs = BsA[BUF];                                               \
        _Pragma("unroll")                                                      \
        for (int ks = 0; ks < 4; ++ks) {                                       \
            const int kb = ks << 3;                                            \
            uint32_t af[2][4];                                                 \
            _Pragma("unroll")                                                  \
            for (int mt = 0; mt < 2; ++mt) {                                   \
                int m = wm * 32 + mt * 16;                                     \
                af[mt][0] = As[(m + g) * 36 + kb + t];                         \
                af[mt][1] = As[(m + g + 8) * 36 + kb + t];                     \
                af[mt][2] = As[(m + g) * 36 + kb + t + 4];                     \
                af[mt][3] = As[(m + g + 8) * 36 + kb + t + 4];                 \
            }                                                                  \
            _Pragma("unroll")                                                  \
            for (int nt = 0; nt < 8; ++nt) {                                   \
                int n = wn * 64 + nt * 8;                                      \
                uint32_t b0, b1;                                               \
                if (BT) {                                                      \
                    b0 = Bs[(n + g) * 36 + kb + t];                            \
                    b1 = Bs[(n + g) * 36 + kb + t + 4];                        \
                } else {                                                       \
                    b0 = Bs[(kb + t) * BSN + n + g];                           \
                    b1 = Bs[(kb + t + 4) * BSN + n + g];                       \
                }                                                              \
                mma_tf32(acc[0][nt], af[0], b0, b1);                           \
                mma_tf32(acc[1][nt], af[1], b0, b1);                           \
            }                                                                  \
        }                                                                      \
    } while (0)

    // ---- pipelined mainloop -------------------------------------------------
    // prologue: chunk0 -> buf0; chunk1 staged in regs
    LDG_CHUNK(0);
    STS_CHUNK(0);
    LDG_CHUNK(1);
    __syncthreads();

    for (int cp = 0; cp < nChunks; cp += 2) {
        // chunk cp (buf0): stage cp+1 into buf1, prefetch cp+2, compute buf0
        STS_CHUNK(1);
        if (cp + 2 < nChunks) LDG_CHUNK(cp + 2);
        COMPUTE_CHUNK(0);
        __syncthreads();
        // chunk cp+1 (buf1): stage cp+2 into buf0, prefetch cp+3, compute buf1
        if (cp + 2 < nChunks) {
            STS_CHUNK(0);
            if (cp + 3 < nChunks) LDG_CHUNK(cp + 3);
        }
        COMPUTE_CHUNK(1);
        __syncthreads();
    }

#undef LDG_CHUNK
#undef STS_CHUNK
#undef COMPUTE_CHUNK

    if (MODE == 1) {
        const float scale = 0.08838834764831845f;   // 1/sqrt(128)
        float rp[4] = {0.f, 0.f, 0.f, 0.f};         // [mt*2 + half]
#pragma unroll
        for (int mt = 0; mt < 2; ++mt)
#pragma unroll
            for (int nt = 0; nt < 8; ++nt)
#pragma unroll
                for (int j = 0; j < 4; ++j) {
                    int lr = wm * 32 + mt * 16 + g + ((j >> 1) << 3);
                    int cg = colg0 + wn * 64 + nt * 8 + (t << 1) + (j & 1);
                    int rg = rowg0 + lr;
                    float e = (cg <= rg) ? __expf(acc[mt][nt][j] * scale) : 0.f;
                    acc[mt][nt][j] = e;
                    rp[mt * 2 + (j >> 1)] += e;
                }
#pragma unroll
        for (int i = 0; i < 4; ++i) {
            rp[i] += __shfl_xor_sync(0xffffffffu, rp[i], 1);
            rp[i] += __shfl_xor_sync(0xffffffffu, rp[i], 2);
        }
        if (t == 0) {
#pragma unroll
            for (int mt = 0; mt < 2; ++mt)
#pragma unroll
                for (int h2 = 0; h2 < 2; ++h2)
                    part[wn * 128 + wm * 32 + mt * 16 + g + (h2 << 3)] = rp[mt * 2 + h2];
        }
        __syncthreads();
        if (tid < 128) partialOut[tid] = part[tid] + part[128 + tid];
    }
    if (MODE == 2) {
#pragma unroll
        for (int mt = 0; mt < 2; ++mt) {
            float i0 = invsum[wm * 32 + mt * 16 + g];
            float i1 = invsum[wm * 32 + mt * 16 + g + 8];
#pragma unroll
            for (int nt = 0; nt < 8; ++nt) {
                acc[mt][nt][0] *= i0; acc[mt][nt][1] *= i0;
                acc[mt][nt][2] *= i1; acc[mt][nt][3] *= i1;
            }
        }
    }

    // epilogue store
#pragma unroll
    for (int mt = 0; mt < 2; ++mt)
#pragma unroll
        for (int nt = 0; nt < 8; ++nt) {
            int row = wm * 32 + mt * 16 + g;
            int col = wn * 64 + nt * 8 + (t << 1);
            *reinterpret_cast<float2*>(C + (size_t)row * ldc + col) =
                make_float2(acc[mt][nt][0], acc[mt][nt][1]);
            *reinterpret_cast<float2*>(C + (size_t)(row + 8) * ldc + col) =
                make_float2(acc[mt][nt][2], acc[mt][nt][3]);
        }
}

// ---- Q projection ----------------------------------------------------------
__global__ void __launch_bounds__(256, 2)
proj_q_kernel(const float* __restrict__ X, const float* __restrict__ Wq)
{
    const int brow = blockIdx.y << 7, bcol = blockIdx.x << 7;
    tf32gemm<false, 0>(X + (size_t)brow * DMODEL, Wq + bcol,
                       g_Q + (size_t)brow * DMODEL + bcol,
                       DMODEL, DMODEL, DMODEL, DMODEL, nullptr, nullptr, 0, 0);
}

// ---- K / V projections -----------------------------------------------------
__global__ void __launch_bounds__(256, 2)
proj_kv_kernel(const float* __restrict__ X,
               const float* __restrict__ Wk,
               const float* __restrict__ Wv)
{
    const int brow = blockIdx.y << 7, bcol = blockIdx.x << 7;
    const float* W = (blockIdx.z == 0) ? Wk : Wv;
    float* O       = (blockIdx.z == 0) ? g_K : g_V;
    tf32gemm<false, 0>(X + (size_t)brow * DMODEL, W + bcol,
                       O + (size_t)brow * KVD + bcol,
                       DMODEL, DMODEL, KVD, KVD, nullptr, nullptr, 0, 0);
}

// ---- RoPE (interleaved), in place on g_Q and g_K ---------------------------
__global__ void rope_kernel()
{
    int idx = blockIdx.x * blockDim.x + threadIdx.x;
    const int qpairs = NTOK * (DMODEL / 2);
    float* ptr;
    int t, p;
    if (idx < qpairs) {
        t = idx >> 10; int c = idx & 1023; p = c & 63;
        ptr = g_Q + (size_t)t * DMODEL + (c << 1);
    } else {
        idx -= qpairs;
        if (idx >= NTOK * (KVD / 2)) return;
        t = idx >> 8; int c = idx & 255; p = c & 63;
        ptr = g_K + (size_t)t * KVD + (c << 1);
    }
    double inv = exp(-(double)p * (9.210340371976184 / 64.0));
    float ang = (float)((double)t * inv);
    float cs = cosf(ang), sn = sinf(ang);
    float xe = ptr[0], xo = ptr[1];
    ptr[0] = xe * cs - xo * sn;
    ptr[1] = xe * sn + xo * cs;
}

// ---- scores + exp + row partials -------------------------------------------
__global__ void __launch_bounds__(256, 2)
qk_kernel()
{
    if (blockIdx.x > blockIdx.y) return;
    const int h = blockIdx.z, brow = blockIdx.y << 7, bcol = blockIdx.x << 7;
    const int kvh = h >> 2, gs = h & 3;
    tf32gemm<true, 1>(g_Q + (size_t)brow * DMODEL + gs * 512 + kvh * 128,
                      g_K + (size_t)bcol * KVD + kvh * 128,
                      g_S + (size_t)h * NTOK * NTOK + (size_t)brow * NTOK + bcol,
                      HDIM, DMODEL, KVD, NTOK,
                      g_partial + ((size_t)h * 16 + blockIdx.x) * NTOK + brow,
                      nullptr, brow, bcol);
}

// ---- reduce per-tile partials to 1/rowsum ----------------------------------
__global__ void __launch_bounds__(256)
rowsum_kernel()
{
    const int idx = blockIdx.x * 256 + threadIdx.x;   // 0..32767
    const int h = idx >> 11, row = idx & 2047;
    const int ntile = (row >> 7) + 1;
    float s = 0.f;
    for (int tt = 0; tt < ntile; ++tt)
        s += g_partial[((size_t)h * 16 + tt) * NTOK + row];
    g_inv[idx] = 1.f / s;
}

// ---- context: C_h = (P_h @ V_h) * inv[row] ---------------------------------
__global__ void __launch_bounds__(256, 2)
pv_kernel()
{
    const int h = blockIdx.z, brow = blockIdx.y << 7;
    const int kvh = h >> 2;
    tf32gemm<false, 2>(g_S + (size_t)h * NTOK * NTOK + (size_t)brow * NTOK,
                       g_V + kvh * 128,
                       g_C + (size_t)brow * DMODEL + h * 128,
                       brow + 128, NTOK, KVD, DMODEL,
                       nullptr, g_inv + h * NTOK + brow, 0, 0);
}

// ---- output projection -----------------------------------------------------
__global__ void __launch_bounds__(256, 2)
out_kernel(const float* __restrict__ Wo, float* __restrict__ out)
{
    const int brow = blockIdx.y << 7, bcol = blockIdx.x << 7;
    tf32gemm<false, 0>(g_C + (size_t)brow * DMODEL, Wo + bcol,
                       out + (size_t)brow * DMODEL + bcol,
                       DMODEL, DMODEL, DMODEL, DMODEL, nullptr, nullptr, 0, 0);
}

extern "C" void kernel_launch(void* const* d_in, const int* in_sizes, int n_in,
                              void* d_out, int out_size)
{
    (void)in_sizes; (void)n_in; (void)out_size;
    const float* x  = (const float*)d_in[0];
    const float* Wq = (const float*)d_in[1];
    const float* Wk = (const float*)d_in[2];
    const float* Wv = (const float*)d_in[3];
    const float* Wo = (const float*)d_in[4];
    float* out = (float*)d_out;

    static int attr_done = 0;
    if (!attr_done) {
        cudaFuncSetAttribute(proj_q_kernel,  cudaFuncAttributeMaxDynamicSharedMemorySize, SMEM_BYTES);
        cudaFuncSetAttribute(proj_kv_kernel, cudaFuncAttributeMaxDynamicSharedMemorySize, SMEM_BYTES);
        cudaFuncSetAttribute(qk_kernel,      cudaFuncAttributeMaxDynamicSharedMemorySize, SMEM_BYTES);
        cudaFuncSetAttribute(pv_kernel,      cudaFuncAttributeMaxDynamicSharedMemorySize, SMEM_BYTES);
        cudaFuncSetAttribute(out_kernel,     cudaFuncAttributeMaxDynamicSharedMemorySize, SMEM_BYTES);
        attr_done = 1;
    }

    proj_q_kernel<<<dim3(DMODEL / 128, NTOK / 128), 256, SMEM_BYTES>>>(x, Wq);
    proj_kv_kernel<<<dim3(KVD / 128, NTOK / 128, 2), 256, SMEM_BYTES>>>(x, Wk, Wv);

    const int total_pairs = NTOK * (DMODEL / 2) + NTOK * (KVD / 2);
    rope_kernel<<<(total_pairs + 255) / 256, 256>>>();

    qk_kernel<<<dim3(NTOK / 128, NTOK / 128, NHEADS), 256, SMEM_BYTES>>>();
    rowsum_kernel<<<NHEADS * NTOK / 256, 256>>>();
    pv_kernel<<<dim3(1, NTOK / 128, NHEADS), 256, SMEM_BYTES>>>();
    out_kernel<<<dim3(DMODEL / 128, NTOK / 128), 256, SMEM_BYTES>>>(Wo, out);
}

// round 12
// speedup vs baseline: 1.3611x; 1.0098x over previous
#include <cuda_runtime.h>
#include <math.h>
#include <stdint.h>

#define NTOK   2048
#define DMODEL 2048
#define KVD    512
#define NHEADS 16
#define HDIM   128

static __device__ float g_Q[NTOK * DMODEL];
static __device__ float g_K[NTOK * KVD];
static __device__ float g_V[NTOK * KVD];
static __device__ float g_S[(size_t)NHEADS * NTOK * NTOK];
static __device__ float g_C[NTOK * DMODEL];
static __device__ float g_partial[(size_t)NHEADS * 16 * NTOK];
static __device__ float g_inv[NHEADS * NTOK];
// tf32 pre-converted operands
static __device__ float g_X[NTOK * DMODEL];
static __device__ float g_Wqc[DMODEL * DMODEL];
static __device__ float g_Wkc[DMODEL * KVD];
static __device__ float g_Wvc[DMODEL * KVD];
static __device__ float g_Woc[DMODEL * DMODEL];

#define BSN      136                // NN B-tile row stride (words)
#define STAGE_A  4608               // one A stage (words) = 128*36
#define STAGE_BT 4608               // one B stage, BT path
#define STAGE_BN (32 * BSN)         // one B stage, NN path = 4352
#define NSTAGE   3
#define SMEM_BYTES ((NSTAGE * STAGE_A + NSTAGE * STAGE_BT) * 4)   // 110592

__device__ __forceinline__ uint32_t f2tf32(float x) {
    uint32_t r;
    asm("cvt.rna.tf32.f32 %0, %1;" : "=r"(r) : "f"(x));
    return r;
}
__device__ __forceinline__ float f2tf32f(float x) { return __uint_as_float(f2tf32(x)); }

__device__ __forceinline__ void cp16(uint32_t saddr, const void* g) {
    asm volatile("cp.async.cg.shared.global [%0], [%1], 16;" :: "r"(saddr), "l"(g));
}
__device__ __forceinline__ void cp_commit() {
    asm volatile("cp.async.commit_group;" ::: "memory");
}
template <int N> __device__ __forceinline__ void cp_wait() {
    asm volatile("cp.async.wait_group %0;" :: "n"(N) : "memory");
}

__device__ __forceinline__ void mma_tf32(float c[4], const uint32_t a[4],
                                         uint32_t b0, uint32_t b1) {
    asm volatile(
        "mma.sync.aligned.m16n8k8.row.col.f32.tf32.tf32.f32 "
        "{%0,%1,%2,%3}, {%4,%5,%6,%7}, {%8,%9}, {%0,%1,%2,%3};"
        : "+f"(c[0]), "+f"(c[1]), "+f"(c[2]), "+f"(c[3])
        : "r"(a[0]), "r"(a[1]), "r"(a[2]), "r"(a[3]), "r"(b0), "r"(b1));
}

// ---------------------------------------------------------------------------
// TF32 tensor-core GEMM, cp.async 3-stage pipeline, one sync per chunk.
// Inputs MUST already be tf32-rounded in gmem. 128x128 tile, 256 threads,
// warp tile 32x64, K chunk 32. Fragment layouts = proven conflict-free ones.
// MODE 0: plain store (final out). MODE 1 (qk): exp+mask+row partials, tf32
// store. MODE 2 (pv): *inv, tf32 store. MODE 3 (proj): tf32 store.
// ---------------------------------------------------------------------------
template <bool BT, int MODE>
__device__ __forceinline__ void tf32gemm(const float* __restrict__ A,
                                         const float* __restrict__ B,
                                         float* __restrict__ C,
                                         int Kdim, int lda, int ldb, int ldc,
                                         float* __restrict__ partialOut,
                                         const float* __restrict__ invsum,
                                         int rowg0, int colg0)
{
    extern __shared__ uint32_t dsm[];
    const int BSTG = BT ? STAGE_BT : STAGE_BN;
    uint32_t* const dsmB = dsm + NSTAGE * STAGE_A;
    const uint32_t sA = (uint32_t)__cvta_generic_to_shared(dsm);
    const uint32_t sB = (uint32_t)__cvta_generic_to_shared(dsmB);
    __shared__ float part[256];                      // MODE 1 only
    const int tid  = threadIdx.x;
    const int lane = tid & 31, wid = tid >> 5;
    const int wm = wid & 3, wn = wid >> 2;
    const int g = lane >> 2, t = lane & 3;
    const int nChunks = Kdim >> 5;

    float acc[2][8][4];
#pragma unroll
    for (int mt = 0; mt < 2; ++mt)
#pragma unroll
        for (int nt = 0; nt < 8; ++nt)
#pragma unroll
            for (int j = 0; j < 4; ++j) acc[mt][nt][j] = 0.f;

    const int r8  = tid >> 3, k8 = (tid & 7) << 2;   // A / BT-B staging coords
    const int rb5 = tid >> 5, n5 = (tid & 31) << 2;  // NN-B staging coords

#define LDGSTS_CHUNK(cc, S)                                                    \
    do {                                                                       \
        const float* An = A + (cc) * 32;                                       \
        const float* Bn = BT ? (B + (cc) * 32) : (B + (size_t)((cc) * 32) * ldb); \
        uint32_t aB = sA + (uint32_t)(S) * (STAGE_A * 4);                      \
        uint32_t bB = sB + (uint32_t)(S) * (BSTG * 4);                         \
        _Pragma("unroll")                                                      \
        for (int i = 0; i < 4; ++i) {                                          \
            int rr = r8 + (i << 5);                                            \
            cp16(aB + (uint32_t)(rr * 36 + k8) * 4, An + (size_t)rr * lda + k8); \
            if (BT) {                                                          \
                cp16(bB + (uint32_t)(rr * 36 + k8) * 4, Bn + (size_t)rr * ldb + k8); \
            } else {                                                           \
                int rbb = rb5 + (i << 3);                                      \
                cp16(bB + (uint32_t)(rbb * BSN + n5) * 4, Bn + (size_t)rbb * ldb + n5); \
            }                                                                  \
        }                                                                      \
        cp_commit();                                                           \
    } while (0)

#define COMPUTE_CHUNK(S)                                                       \
    do {                                                                       \
        const uint32_t* As = dsm + (S) * STAGE_A;                              \
        const uint32_t* Bs = dsmB + (S) * BSTG;                                \
        _Pragma("unroll")                                                      \
        for (int ks = 0; ks < 4; ++ks) {                                       \
            const int kb = ks << 3;                                            \
            uint32_t af[2][4];                                                 \
            _Pragma("unroll")                                                  \
            for (int mt = 0; mt < 2; ++mt) {                                   \
                int m = wm * 32 + mt * 16;                                     \
                af[mt][0] = As[(m + g) * 36 + kb + t];                         \
                af[mt][1] = As[(m + g + 8) * 36 + kb + t];                     \
                af[mt][2] = As[(m + g) * 36 + kb + t + 4];                     \
                af[mt][3] = As[(m + g + 8) * 36 + kb + t + 4];                 \
            }                                                                  \
            _Pragma("unroll")                                                  \
            for (int nt = 0; nt < 8; ++nt) {                                   \
                int n = wn * 64 + nt * 8;                                      \
                uint32_t b0, b1;                                               \
                if (BT) {                                                      \
                    b0 = Bs[(n + g) * 36 + kb + t];                            \
                    b1 = Bs[(n + g) * 36 + kb + t + 4];                        \
                } else {                                                       \
                    b0 = Bs[(kb + t) * BSN + n + g];                           \
                    b1 = Bs[(kb + t + 4) * BSN + n + g];                       \
                }                                                              \
                mma_tf32(acc[0][nt], af[0], b0, b1);                           \
                mma_tf32(acc[1][nt], af[1], b0, b1);                           \
            }                                                                  \
        }                                                                      \
    } while (0)

    // prologue: chunks 0,1 in flight
    LDGSTS_CHUNK(0, 0);
    LDGSTS_CHUNK(1, 1);

    int scur = 0, snxt = 2;   // stage of chunk c, stage of chunk c+2
    for (int c = 0; c < nChunks; ++c) {
        if (c + 1 < nChunks) cp_wait<1>(); else cp_wait<0>();
        __syncthreads();
        if (c + 2 < nChunks) LDGSTS_CHUNK(c + 2, snxt);
        COMPUTE_CHUNK(scur);
        scur = (scur == NSTAGE - 1) ? 0 : scur + 1;
        snxt = (snxt == NSTAGE - 1) ? 0 : snxt + 1;
    }
    __syncthreads();

#undef LDGSTS_CHUNK
#undef COMPUTE_CHUNK

    if (MODE == 1) {
        const float scale = 0.08838834764831845f;   // 1/sqrt(128)
        float rp[4] = {0.f, 0.f, 0.f, 0.f};
#pragma unroll
        for (int mt = 0; mt < 2; ++mt)
#pragma unroll
            for (int nt = 0; nt < 8; ++nt)
#pragma unroll
                for (int j = 0; j < 4; ++j) {
                    int lr = wm * 32 + mt * 16 + g + ((j >> 1) << 3);
                    int cg = colg0 + wn * 64 + nt * 8 + (t << 1) + (j & 1);
                    int rg = rowg0 + lr;
                    float e = (cg <= rg) ? __expf(acc[mt][nt][j] * scale) : 0.f;
                    acc[mt][nt][j] = e;
                    rp[mt * 2 + (j >> 1)] += e;
                }
#pragma unroll
        for (int i = 0; i < 4; ++i) {
            rp[i] += __shfl_xor_sync(0xffffffffu, rp[i], 1);
            rp[i] += __shfl_xor_sync(0xffffffffu, rp[i], 2);
        }
        if (t == 0) {
#pragma unroll
            for (int mt = 0; mt < 2; ++mt)
#pragma unroll
                for (int h2 = 0; h2 < 2; ++h2)
                    part[wn * 128 + wm * 32 + mt * 16 + g + (h2 << 3)] = rp[mt * 2 + h2];
        }
        __syncthreads();
        if (tid < 128) partialOut[tid] = part[tid] + part[128 + tid];
    }
    if (MODE == 2) {
#pragma unroll
        for (int mt = 0; mt < 2; ++mt) {
            float i0 = invsum[wm * 32 + mt * 16 + g];
            float i1 = invsum[wm * 32 + mt * 16 + g + 8];
#pragma unroll
            for (int nt = 0; nt < 8; ++nt) {
                acc[mt][nt][0] *= i0; acc[mt][nt][1] *= i0;
                acc[mt][nt][2] *= i1; acc[mt][nt][3] *= i1;
            }
        }
    }

    // epilogue store (MODE 1/2/3 store tf32-rounded for downstream GEMMs)
#pragma unroll
    for (int mt = 0; mt < 2; ++mt)
#pragma unroll
        for (int nt = 0; nt < 8; ++nt) {
            int row = wm * 32 + mt * 16 + g;
            int col = wn * 64 + nt * 8 + (t << 1);
            float v0 = acc[mt][nt][0], v1 = acc[mt][nt][1];
            float v2 = acc[mt][nt][2], v3 = acc[mt][nt][3];
            if (MODE != 0) {
                v0 = f2tf32f(v0); v1 = f2tf32f(v1);
                v2 = f2tf32f(v2); v3 = f2tf32f(v3);
            }
            *reinterpret_cast<float2*>(C + (size_t)row * ldc + col) = make_float2(v0, v1);
            *reinterpret_cast<float2*>(C + (size_t)(row + 8) * ldc + col) = make_float2(v2, v3);
        }
}

// ---- elementwise tf32 conversion -------------------------------------------
__global__ void __launch_bounds__(256)
cvt_tf32_kernel(const float4* __restrict__ in, float4* __restrict__ out, int n4)
{
    int i = blockIdx.x * 256 + threadIdx.x;
    if (i < n4) {
        float4 v = in[i];
        v.x = f2tf32f(v.x); v.y = f2tf32f(v.y);
        v.z = f2tf32f(v.z); v.w = f2tf32f(v.w);
        out[i] = v;
    }
}

// ---- Q projection ----------------------------------------------------------
__global__ void __launch_bounds__(256, 2)
proj_q_kernel()
{
    const int brow = blockIdx.y << 7, bcol = blockIdx.x << 7;
    tf32gemm<false, 3>(g_X + (size_t)brow * DMODEL, g_Wqc + bcol,
                       g_Q + (size_t)brow * DMODEL + bcol,
                       DMODEL, DMODEL, DMODEL, DMODEL, nullptr, nullptr, 0, 0);
}

// ---- K / V projections -----------------------------------------------------
__global__ void __launch_bounds__(256, 2)
proj_kv_kernel()
{
    const int brow = blockIdx.y << 7, bcol = blockIdx.x << 7;
    const float* W = (blockIdx.z == 0) ? g_Wkc : g_Wvc;
    float* O       = (blockIdx.z == 0) ? g_K : g_V;
    tf32gemm<false, 3>(g_X + (size_t)brow * DMODEL, W + bcol,
                       O + (size_t)brow * KVD + bcol,
                       DMODEL, DMODEL, KVD, KVD, nullptr, nullptr, 0, 0);
}

// ---- RoPE (interleaved), in place, stores tf32-rounded ---------------------
__global__ void rope_kernel()
{
    int idx = blockIdx.x * blockDim.x + threadIdx.x;
    const int qpairs = NTOK * (DMODEL / 2);
    float* ptr;
    int t, p;
    if (idx < qpairs) {
        t = idx >> 10; int c = idx & 1023; p = c & 63;
        ptr = g_Q + (size_t)t * DMODEL + (c << 1);
    } else {
        idx -= qpairs;
        if (idx >= NTOK * (KVD / 2)) return;
        t = idx >> 8; int c = idx & 255; p = c & 63;
        ptr = g_K + (size_t)t * KVD + (c << 1);
    }
    double inv = exp(-(double)p * (9.210340371976184 / 64.0));
    float ang = (float)((double)t * inv);
    float cs = cosf(ang), sn = sinf(ang);
    float xe = ptr[0], xo = ptr[1];
    ptr[0] = f2tf32f(xe * cs - xo * sn);
    ptr[1] = f2tf32f(xe * sn + xo * cs);
}

// ---- scores + exp + row partials -------------------------------------------
__global__ void __launch_bounds__(256, 2)
qk_kernel()
{
    if (blockIdx.x > blockIdx.y) return;
    const int h = blockIdx.z, brow = blockIdx.y << 7, bcol = blockIdx.x << 7;
    const int kvh = h >> 2, gs = h & 3;
    tf32gemm<true, 1>(g_Q + (size_t)brow * DMODEL + gs * 512 + kvh * 128,
                      g_K + (size_t)bcol * KVD + kvh * 128,
                      g_S + (size_t)h * NTOK * NTOK + (size_t)brow * NTOK + bcol,
                      HDIM, DMODEL, KVD, NTOK,
                      g_partial + ((size_t)h * 16 + blockIdx.x) * NTOK + brow,
                      nullptr, brow, bcol);
}

// ---- reduce per-tile partials to 1/rowsum ----------------------------------
__global__ void __launch_bounds__(256)
rowsum_kernel()
{
    const int idx = blockIdx.x * 256 + threadIdx.x;
    const int h = idx >> 11, row = idx & 2047;
    const int ntile = (row >> 7) + 1;
    float s = 0.f;
    for (int tt = 0; tt < ntile; ++tt)
        s += g_partial[((size_t)h * 16 + tt) * NTOK + row];
    g_inv[idx] = 1.f / s;
}

// ---- context: C_h = (P_h @ V_h) * inv[row] ---------------------------------
__global__ void __launch_bounds__(256, 2)
pv_kernel()
{
    const int h = blockIdx.z, brow = blockIdx.y << 7;
    const int kvh = h >> 2;
    tf32gemm<false, 2>(g_S + (size_t)h * NTOK * NTOK + (size_t)brow * NTOK,
                       g_V + kvh * 128,
                       g_C + (size_t)brow * DMODEL + h * 128,
                       brow + 128, NTOK, KVD, DMODEL,
                       nullptr, g_inv + h * NTOK + brow, 0, 0);
}

// ---- output projection -----------------------------------------------------
__global__ void __launch_bounds__(256, 2)
out_kernel(float* __restrict__ out)
{
    const int brow = blockIdx.y << 7, bcol = blockIdx.x << 7;
    tf32gemm<false, 0>(g_C + (size_t)brow * DMODEL, g_Woc + bcol,
                       out + (size_t)brow * DMODEL + bcol,
                       DMODEL, DMODEL, DMODEL, DMODEL, nullptr, nullptr, 0, 0);
}

extern "C" void kernel_launch(void* const* d_in, const int* in_sizes, int n_in,
                              void* d_out, int out_size)
{
    (void)in_sizes; (void)n_in; (void)out_size;
    const float* x  = (const float*)d_in[0];
    const float* Wq = (const float*)d_in[1];
    const float* Wk = (const float*)d_in[2];
    const float* Wv = (const float*)d_in[3];
    const float* Wo = (const float*)d_in[4];
    float* out = (float*)d_out;

    static int attr_done = 0;
    if (!attr_done) {
        cudaFuncSetAttribute(proj_q_kernel,  cudaFuncAttributeMaxDynamicSharedMemorySize, SMEM_BYTES);
        cudaFuncSetAttribute(proj_kv_kernel, cudaFuncAttributeMaxDynamicSharedMemorySize, SMEM_BYTES);
        cudaFuncSetAttribute(qk_kernel,      cudaFuncAttributeMaxDynamicSharedMemorySize, SMEM_BYTES);
        cudaFuncSetAttribute(pv_kernel,      cudaFuncAttributeMaxDynamicSharedMemorySize, SMEM_BYTES);
        cudaFuncSetAttribute(out_kernel,     cudaFuncAttributeMaxDynamicSharedMemorySize, SMEM_BYTES);
        attr_done = 1;
    }

    float *pX, *pWq, *pWk, *pWv, *pWo;
    cudaGetSymbolAddress((void**)&pX,  g_X);
    cudaGetSymbolAddress((void**)&pWq, g_Wqc);
    cudaGetSymbolAddress((void**)&pWk, g_Wkc);
    cudaGetSymbolAddress((void**)&pWv, g_Wvc);
    cudaGetSymbolAddress((void**)&pWo, g_Woc);

    const int n4_big = NTOK * DMODEL / 4;            // 1M float4
    const int n4_kv  = DMODEL * KVD / 4;             // 256K float4
    cvt_tf32_kernel<<<(n4_big + 255) / 256, 256>>>((const float4*)x,  (float4*)pX,  n4_big);
    cvt_tf32_kernel<<<(n4_big + 255) / 256, 256>>>((const float4*)Wq, (float4*)pWq, n4_big);
    cvt_tf32_kernel<<<(n4_kv + 255) / 256, 256>>>((const float4*)Wk, (float4*)pWk, n4_kv);
    cvt_tf32_kernel<<<(n4_kv + 255) / 256, 256>>>((const float4*)Wv, (float4*)pWv, n4_kv);
    cvt_tf32_kernel<<<(n4_big + 255) / 256, 256>>>((const float4*)Wo, (float4*)pWo, n4_big);

    proj_q_kernel<<<dim3(DMODEL / 128, NTOK / 128), 256, SMEM_BYTES>>>();
    proj_kv_kernel<<<dim3(KVD / 128, NTOK / 128, 2), 256, SMEM_BYTES>>>();

    const int total_pairs = NTOK * (DMODEL / 2) + NTOK * (KVD / 2);
    rope_kernel<<<(total_pairs + 255) / 256, 256>>>();

    qk_kernel<<<dim3(NTOK / 128, NTOK / 128, NHEADS), 256, SMEM_BYTES>>>();
    rowsum_kernel<<<NHEADS * NTOK / 256, 256>>>();
    pv_kernel<<<dim3(1, NTOK / 128, NHEADS), 256, SMEM_BYTES>>>();
    out_kernel<<<dim3(DMODEL / 128, NTOK / 128), 256, SMEM_BYTES>>>(out);
}